// round 2
// baseline (speedup 1.0000x reference)
#include <cuda_runtime.h>
#include <cuda_bf16.h>

#define DIN  128
#define DOUT 64
#define MAX_N 100000

// Scratch for the dense projection result (support = X @ W). Static __device__
// array per the no-allocation rule.
__device__ float g_support[(size_t)MAX_N * DOUT];

// ---------------------------------------------------------------------------
// Kernel 1: out[r][c] = bias[c]  (d_out is poisoned; SpMM accumulates on top)
// ---------------------------------------------------------------------------
__global__ __launch_bounds__(256) void init_out_kernel(float* __restrict__ out,
                                                       const float* __restrict__ bias,
                                                       int n_vec4) {
    int i = blockIdx.x * blockDim.x + threadIdx.x;   // one float4 per thread
    if (i >= n_vec4) return;
    int cg = i & (DOUT / 4 - 1);                     // column group 0..15
    float4 b = ((const float4*)bias)[cg];
    ((float4*)out)[i] = b;
}

// ---------------------------------------------------------------------------
// Kernel 2: support = X @ W    (N x 128) @ (128 x 64)
// Block: 256 threads, handles 128 rows. W staged in shared once (32 KB).
// Thread layout per 16-row pass: tid = ty*16 + cg; computes 1 row x 4 cols.
// Inner loop per k: 1 LDS (x broadcast) + 1 LDS.128 (w) + 4 FFMA.
// ---------------------------------------------------------------------------
#define ROWS_PER_BLOCK 128
#define PASS_ROWS 16

__global__ __launch_bounds__(256) void gemm_kernel(const float* __restrict__ x,
                                                   const float* __restrict__ w,
                                                   float* __restrict__ support,
                                                   int N) {
    __shared__ __align__(16) float sW[DIN * DOUT];      // 32 KB
    __shared__ __align__(16) float sX[PASS_ROWS][DIN];  // 8 KB

    int tid = threadIdx.x;

    // Cooperative load of the full weight matrix (float4, coalesced).
    for (int i = tid; i < DIN * DOUT / 4; i += 256) {
        ((float4*)sW)[i] = ((const float4*)w)[i];
    }

    int block_row = blockIdx.x * ROWS_PER_BLOCK;
    int cg = tid & 15;    // column group: cols cg*4 .. cg*4+3
    int ty = tid >> 4;    // row within pass: 0..15

    for (int pass = 0; pass < ROWS_PER_BLOCK / PASS_ROWS; ++pass) {
        int r0 = block_row + pass * PASS_ROWS;
        __syncthreads();
        // Load 16 rows of X (16*128 floats = 512 float4s, 2 per thread).
        for (int i = tid; i < PASS_ROWS * DIN / 4; i += 256) {
            int rr = i >> 5;              // i / (DIN/4) with DIN/4 = 32
            int kk = i & 31;
            int gr = r0 + rr;
            float4 v = (gr < N) ? ((const float4*)x)[(size_t)gr * (DIN / 4) + kk]
                                : make_float4(0.f, 0.f, 0.f, 0.f);
            ((float4*)sX[rr])[kk] = v;
        }
        __syncthreads();

        float acc0 = 0.f, acc1 = 0.f, acc2 = 0.f, acc3 = 0.f;
        #pragma unroll 8
        for (int k = 0; k < DIN; ++k) {
            float xv = sX[ty][k];
            float4 wv = *(const float4*)&sW[k * DOUT + cg * 4];
            acc0 += xv * wv.x;
            acc1 += xv * wv.y;
            acc2 += xv * wv.z;
            acc3 += xv * wv.w;
        }
        int gr = r0 + ty;
        if (gr < N) {
            *(float4*)&support[(size_t)gr * DOUT + cg * 4] =
                make_float4(acc0, acc1, acc2, acc3);
        }
    }
}

// ---------------------------------------------------------------------------
// Kernel 3: SpMM scatter-add.
// One lane per (edge, 4 columns): 16 lanes cover one edge's 64 columns.
// float4 gather of support (L2-resident) + float4 atomicAdd (sm_90+ REDG.128).
// ---------------------------------------------------------------------------
__global__ __launch_bounds__(256) void spmm_kernel(const int* __restrict__ edge_index,
                                                   const float* __restrict__ vals,
                                                   const float* __restrict__ support,
                                                   float* __restrict__ out,
                                                   int E) {
    int t = blockIdx.x * blockDim.x + threadIdx.x;
    int e = t >> 4;
    if (e >= E) return;
    int d = (t & 15) * 4;

    int r = edge_index[e];       // destination row
    int c = edge_index[E + e];   // source row
    float v = vals[e];

    float4 s = *(const float4*)&support[(size_t)c * DOUT + d];
    float4 m = make_float4(v * s.x, v * s.y, v * s.z, v * s.w);
    atomicAdd((float4*)&out[(size_t)r * DOUT + d], m);
}

// ---------------------------------------------------------------------------
// kernel_launch
// Inputs (metadata order): input [N*128 f32], edge_index [2*E i32],
//                          edge_vals [E f32], weight [128*64 f32], bias [64 f32]
// Output: [N*64 f32]
// ---------------------------------------------------------------------------
extern "C" void kernel_launch(void* const* d_in, const int* in_sizes, int n_in,
                              void* d_out, int out_size) {
    const float* x    = (const float*)d_in[0];
    const int*   ei   = (const int*)d_in[1];
    const float* vals = (const float*)d_in[2];
    const float* w    = (const float*)d_in[3];
    const float* bias = (const float*)d_in[4];
    float* out = (float*)d_out;

    int N = in_sizes[0] / DIN;   // 100000
    int E = in_sizes[2];         // 1000000

    float* support;
    cudaGetSymbolAddress((void**)&support, g_support);

    // 1. out = bias (broadcast)
    int n_vec4 = N * (DOUT / 4);
    init_out_kernel<<<(n_vec4 + 255) / 256, 256>>>(out, bias, n_vec4);

    // 2. support = X @ W
    int gemm_blocks = (N + ROWS_PER_BLOCK - 1) / ROWS_PER_BLOCK;
    gemm_kernel<<<gemm_blocks, 256>>>(x, w, support, N);

    // 3. scatter-add over edges
    long long spmm_threads = (long long)E * 16;
    int spmm_blocks = (int)((spmm_threads + 255) / 256);
    spmm_kernel<<<spmm_blocks, 256>>>(ei, vals, support, out, E);
}